// round 4
// baseline (speedup 1.0000x reference)
#include <cuda_runtime.h>
#include <math.h>

#define NT 4
#define PT 8192
#define NH 32
#define NU 128

typedef unsigned long long ull;

// ---------------- f32x2 packed helpers ----------------
__device__ __forceinline__ ull pk2(float lo, float hi) {
    ull r;
    asm("mov.b64 %0, {%1, %2};" : "=l"(r) : "f"(lo), "f"(hi));
    return r;
}
__device__ __forceinline__ void upk2(ull v, float& lo, float& hi) {
    asm("mov.b64 {%0, %1}, %2;" : "=f"(lo), "=f"(hi) : "l"(v));
}
__device__ __forceinline__ ull ffma2(ull a, ull b, ull c) {
    ull d;
    asm("fma.rn.f32x2 %0, %1, %2, %3;" : "=l"(d) : "l"(a), "l"(b), "l"(c));
    return d;
}

// ---------------- scratch (device globals; no allocations) ----------------
__device__ float g_KT[NT * NU * NU];           // k_w transposed per type
__device__ float g_QK[NT * NU * NU];           // q_w @ k_w^T
__device__ float g_VF[NT * NU * NU];           // v_w @ fc_w
__device__ float g_Q[(size_t)NT * PT * NU];    // 16 MB: q = x @ q_w
__device__ float g_QKX[(size_t)NT * PT * NU];  // 16 MB: x @ QK
__device__ float g_HB[(size_t)NT * PT * NU];   // 16 MB: attn-weighted hist
__device__ float g_RAW[(size_t)NT * PT * NH];  // 4 MB: raw attention scores
__device__ float g_M[NT * NH];
__device__ float g_S[NT * NH];

// ---------------- K0a: transpose k_w per type ----------------
__global__ void __launch_bounds__(256) ktrans(const float* __restrict__ kw) {
    __shared__ float tile[32][33];
    int t = blockIdx.z;
    int bx = blockIdx.x * 32, by = blockIdx.y * 32;
    const float* src = kw + (size_t)t * NU * NU;
    float* dst = g_KT + (size_t)t * NU * NU;
    int tx = threadIdx.x, ty = threadIdx.y;
#pragma unroll
    for (int i = 0; i < 32; i += 8)
        tile[ty + i][tx] = src[(by + ty + i) * NU + bx + tx];
    __syncthreads();
#pragma unroll
    for (int i = 0; i < 32; i += 8)
        dst[(bx + ty + i) * NU + by + tx] = tile[tx][ty + i];
}

// ---------------- K0b: QK[t][e][u] = sum_v q_w[t][e][v] * k_w[t][u][v] ----------------
__global__ void __launch_bounds__(128) kqk(const float* __restrict__ qw) {
    int t = blockIdx.y, e = blockIdx.x, u = threadIdx.x;
    const float* q = qw + ((size_t)t * NU + e) * NU;
    const float* kt = g_KT + (size_t)t * NU * NU;
    float acc = 0.f;
#pragma unroll 8
    for (int v = 0; v < NU; ++v)
        acc = fmaf(q[v], kt[v * NU + u], acc);
    g_QK[((size_t)t * NU + e) * NU + u] = acc;
}

// ---------------- K0c: VF[t][w][j] = sum_u v_w[t][w][u] * fc_w[t][u][j] ----------------
__global__ void __launch_bounds__(128) kvf(const float* __restrict__ vw,
                                           const float* __restrict__ fw) {
    int t = blockIdx.y, w = blockIdx.x, j = threadIdx.x;
    const float* vr = vw + ((size_t)t * NU + w) * NU;
    const float* f = fw + (size_t)t * NU * NU;
    float acc = 0.f;
#pragma unroll 8
    for (int u = 0; u < NU; ++u)
        acc = fmaf(vr[u], f[u * NU + j], acc);
    g_VF[((size_t)t * NU + w) * NU + j] = acc;
}

// ============ kgemm2: qkx = x@QK and q = x@qw, f32x2-packed, two W phases ============
// 256 thr = 8 warps, M-tile 32 (4 rows/warp). smem: W 64KB + X 16KB = 80KB -> 2 CTAs/SM.
__global__ void __launch_bounds__(256, 2) kgemm2(const float* __restrict__ state,
                                                 const int* __restrict__ eidx,
                                                 const float* __restrict__ qw) {
    extern __shared__ float sm[];
    float* sW = sm;                  // 16384 floats
    float* sX = sm + 16384;          // 32*128
    float4* sW4 = (float4*)sW;
    int t = blockIdx.y;
    int n0 = blockIdx.x * 32;
    int tid = threadIdx.x;
    int lane = tid & 31, warp = tid >> 5;
    int r0 = warp * 4;

    // gather x rows
    float4* sX4 = (float4*)sX;
#pragma unroll
    for (int i = tid; i < 1024; i += 256) {
        int r = i >> 5, c = i & 31;
        int idx = eidx[t * PT + n0 + r];
        sX4[i] = __ldg((const float4*)(state + (size_t)idx * NU) + c);
    }

#pragma unroll
    for (int phase = 0; phase < 2; ++phase) {
        __syncthreads();
        const float4* wsrc = phase == 0 ? (const float4*)(g_QK + (size_t)t * NU * NU)
                                        : (const float4*)(qw + (size_t)t * NU * NU);
#pragma unroll
        for (int i = tid; i < 4096; i += 256) sW4[i] = wsrc[i];
        __syncthreads();

        ull acc[4][4];
#pragma unroll
        for (int e = 0; e < 4; ++e)
#pragma unroll
            for (int c = 0; c < 4; ++c) acc[e][c] = 0ull;

#pragma unroll 8
        for (int v2 = 0; v2 < 64; ++v2) {
            float4 b0 = sW4[(2 * v2) * 32 + lane];
            float4 b1 = sW4[(2 * v2 + 1) * 32 + lane];
            ull bx = pk2(b0.x, b1.x), by = pk2(b0.y, b1.y);
            ull bz = pk2(b0.z, b1.z), bw = pk2(b0.w, b1.w);
#pragma unroll
            for (int e = 0; e < 4; ++e) {
                ull ap = *(const ull*)&sX[(r0 + e) * NU + 2 * v2];  // LDS.64 broadcast
                acc[e][0] = ffma2(ap, bx, acc[e][0]);
                acc[e][1] = ffma2(ap, by, acc[e][1]);
                acc[e][2] = ffma2(ap, bz, acc[e][2]);
                acc[e][3] = ffma2(ap, bw, acc[e][3]);
            }
        }

        float* dst = phase == 0 ? g_QKX : g_Q;
#pragma unroll
        for (int e = 0; e < 4; ++e) {
            float lo, hi;
            float4 o;
            upk2(acc[e][0], lo, hi); o.x = lo + hi;
            upk2(acc[e][1], lo, hi); o.y = lo + hi;
            upk2(acc[e][2], lo, hi); o.z = lo + hi;
            upk2(acc[e][3], lo, hi); o.w = lo + hi;
            ((float4*)(dst + ((size_t)t * PT + n0 + r0 + e) * NU))[lane] = o;
        }
    }
}

// ============ K1b: raw[h] = hist[idx][h][:] . qkx  (pure hist stream) ============
__global__ void __launch_bounds__(128) k1b(const float* __restrict__ hist,
                                           const int* __restrict__ eidx) {
    int lane = threadIdx.x & 31;
    int warp = threadIdx.x >> 5;
    int t = blockIdx.y;
    int n = blockIdx.x * 4 + warp;
    int idx = eidx[t * PT + n];

    float4 qkl = ((const float4*)(g_QKX + ((size_t)t * PT + n) * NU))[lane];
    const float4* h4 = (const float4*)(hist + (size_t)idx * NH * NU);
    float myraw = 0.f;
#pragma unroll 8
    for (int h = 0; h < NH; ++h) {
        float4 r4 = __ldcs(h4 + h * 32 + lane);
        float p = fmaf(r4.x, qkl.x, fmaf(r4.y, qkl.y, fmaf(r4.z, qkl.z, r4.w * qkl.w)));
#pragma unroll
        for (int o = 16; o; o >>= 1) p += __shfl_xor_sync(0xffffffffu, p, o);
        if (lane == h) myraw = p;
    }
    g_RAW[((size_t)t * PT + n) * NH + lane] = myraw;
}

// ---------------- K2: online single-pass max+sumexp per (t,h) ----------------
__global__ void __launch_bounds__(256) k2() {
    int th = blockIdx.x;
    const float* base = g_RAW + ((size_t)(th >> 5)) * PT * NH + (th & 31);
    __shared__ float rm[256], rs[256];
    int tid = threadIdx.x;

    float m = -3.402823466e+38f, s = 0.f;
    for (int n = tid; n < PT; n += 256) {
        float x = base[(size_t)n * NH];
        if (x > m) { s = s * expf(m - x) + 1.f; m = x; }
        else s += expf(x - m);
    }
    rm[tid] = m; rs[tid] = s;
    __syncthreads();
#pragma unroll
    for (int st = 128; st; st >>= 1) {
        if (tid < st) {
            float m2 = rm[tid + st], s2 = rs[tid + st];
            float M = fmaxf(rm[tid], m2);
            rs[tid] = rs[tid] * expf(rm[tid] - M) + s2 * expf(m2 - M);
            rm[tid] = M;
        }
        __syncthreads();
    }
    if (tid == 0) { g_M[th] = rm[0]; g_S[th] = rs[0]; }
}

// ============ K3a: hbar = attn^T hist  (pure hist stream) ============
__global__ void __launch_bounds__(128) k3a(const float* __restrict__ hist,
                                           const int* __restrict__ eidx) {
    __shared__ float sw[4][NH];
    int lane = threadIdx.x & 31;
    int warp = threadIdx.x >> 5;
    int t = blockIdx.y;
    int n = blockIdx.x * 4 + warp;
    int idx = eidx[t * PT + n];

    {
        float r = g_RAW[((size_t)t * PT + n) * NH + lane];
        sw[warp][lane] = expf(r - g_M[t * NH + lane]) / g_S[t * NH + lane];
    }
    __syncwarp();

    const float4* h4 = (const float4*)(hist + (size_t)idx * NH * NU);
    float4 hb = make_float4(0.f, 0.f, 0.f, 0.f);
#pragma unroll 8
    for (int h = 0; h < NH; ++h) {
        float4 r4 = __ldcs(h4 + h * 32 + lane);
        float wh = sw[warp][h];
        hb.x = fmaf(wh, r4.x, hb.x); hb.y = fmaf(wh, r4.y, hb.y);
        hb.z = fmaf(wh, r4.z, hb.z); hb.w = fmaf(wh, r4.w, hb.w);
    }
    ((float4*)(g_HB + ((size_t)t * PT + n) * NU))[lane] = hb;
}

// ============ kout2: out = relu(HB @ VF) + q   (f32x2 GEMV + epilogue) ============
// 256 thr, M-tile 32, smem: VF 64KB + HB 16KB = 80KB -> 2 CTAs/SM.
__global__ void __launch_bounds__(256, 2) kout2(float* __restrict__ out) {
    extern __shared__ float sm[];
    float* sW = sm;
    float* sX = sm + 16384;
    float4* sW4 = (float4*)sW;
    int t = blockIdx.y;
    int n0 = blockIdx.x * 32;
    int tid = threadIdx.x;
    int lane = tid & 31, warp = tid >> 5;
    int r0 = warp * 4;

    {
        const float4* wsrc = (const float4*)(g_VF + (size_t)t * NU * NU);
#pragma unroll
        for (int i = tid; i < 4096; i += 256) sW4[i] = wsrc[i];
        const float4* x4 = (const float4*)(g_HB + ((size_t)t * PT + n0) * NU);
        float4* sX4 = (float4*)sX;
#pragma unroll
        for (int i = tid; i < 1024; i += 256) sX4[i] = x4[i];
    }
    __syncthreads();

    ull acc[4][4];
#pragma unroll
    for (int e = 0; e < 4; ++e)
#pragma unroll
        for (int c = 0; c < 4; ++c) acc[e][c] = 0ull;

#pragma unroll 8
    for (int v2 = 0; v2 < 64; ++v2) {
        float4 b0 = sW4[(2 * v2) * 32 + lane];
        float4 b1 = sW4[(2 * v2 + 1) * 32 + lane];
        ull bx = pk2(b0.x, b1.x), by = pk2(b0.y, b1.y);
        ull bz = pk2(b0.z, b1.z), bw = pk2(b0.w, b1.w);
#pragma unroll
        for (int e = 0; e < 4; ++e) {
            ull ap = *(const ull*)&sX[(r0 + e) * NU + 2 * v2];
            acc[e][0] = ffma2(ap, bx, acc[e][0]);
            acc[e][1] = ffma2(ap, by, acc[e][1]);
            acc[e][2] = ffma2(ap, bz, acc[e][2]);
            acc[e][3] = ffma2(ap, bw, acc[e][3]);
        }
    }

#pragma unroll
    for (int e = 0; e < 4; ++e) {
        size_t row = (size_t)t * PT + n0 + r0 + e;
        float4 q4 = ((const float4*)(g_Q + row * NU))[lane];
        float lo, hi;
        float4 o;
        upk2(acc[e][0], lo, hi); o.x = fmaxf(lo + hi, 0.f) + q4.x;
        upk2(acc[e][1], lo, hi); o.y = fmaxf(lo + hi, 0.f) + q4.y;
        upk2(acc[e][2], lo, hi); o.z = fmaxf(lo + hi, 0.f) + q4.z;
        upk2(acc[e][3], lo, hi); o.w = fmaxf(lo + hi, 0.f) + q4.w;
        ((float4*)(out + row * NU))[lane] = o;
    }
}

// ---------------- launch ----------------
extern "C" void kernel_launch(void* const* d_in, const int* in_sizes, int n_in,
                              void* d_out, int out_size) {
    const float* state = (const float*)d_in[0];
    const float* hist  = (const float*)d_in[1];
    const int*   eidx  = (const int*)d_in[2];
    const float* qw    = (const float*)d_in[3];
    const float* kw    = (const float*)d_in[4];
    const float* vw    = (const float*)d_in[5];
    const float* fw    = (const float*)d_in[6];
    float* out = (float*)d_out;

    const int GSMEM = (16384 + 4096) * 4;  // 80 KB
    static bool attr_done = false;
    if (!attr_done) {
        cudaFuncSetAttribute(kgemm2, cudaFuncAttributeMaxDynamicSharedMemorySize, GSMEM);
        cudaFuncSetAttribute(kout2, cudaFuncAttributeMaxDynamicSharedMemorySize, GSMEM);
        attr_done = true;
    }

    ktrans<<<dim3(4, 4, NT), dim3(32, 8)>>>(kw);
    kqk<<<dim3(NU, NT), NU>>>(qw);
    kvf<<<dim3(NU, NT), NU>>>(vw, fw);
    kgemm2<<<dim3(PT / 32, NT), 256, GSMEM>>>(state, eidx, qw);
    k1b<<<dim3(PT / 4, NT), 128>>>(hist, eidx);
    k2<<<NT * NH, 256>>>();
    k3a<<<dim3(PT / 4, NT), 128>>>(hist, eidx);
    kout2<<<dim3(PT / 32, NT), 256, GSMEM>>>(out);
}

// round 5
// speedup vs baseline: 1.1292x; 1.1292x over previous
#include <cuda_runtime.h>
#include <math.h>

#define NT 4
#define PT 8192
#define NH 32
#define NU 128

// ---------------- scratch (device globals; no allocations) ----------------
__device__ float g_KT[NT * NU * NU];           // k_w transposed per type
__device__ float g_QK[NT * NU * NU];           // q_w @ k_w^T
__device__ float g_VF[NT * NU * NU];           // v_w @ fc_w
__device__ float g_Q[(size_t)NT * PT * NU];    // 16 MB: q = x @ q_w
__device__ float g_QKX[(size_t)NT * PT * NU];  // 16 MB: x @ QK
__device__ float g_HB[(size_t)NT * PT * NU];   // 16 MB: attn-weighted hist
__device__ float g_RAW[(size_t)NT * PT * NH];  // 4 MB: raw scores
__device__ float g_M[NT * NH];
__device__ float g_S[NT * NH];

// ---------------- prep ----------------
__global__ void __launch_bounds__(256) ktrans(const float* __restrict__ kw) {
    __shared__ float tile[32][33];
    int t = blockIdx.z;
    int bx = blockIdx.x * 32, by = blockIdx.y * 32;
    const float* src = kw + (size_t)t * NU * NU;
    float* dst = g_KT + (size_t)t * NU * NU;
    int tx = threadIdx.x, ty = threadIdx.y;
#pragma unroll
    for (int i = 0; i < 32; i += 8)
        tile[ty + i][tx] = src[(by + ty + i) * NU + bx + tx];
    __syncthreads();
#pragma unroll
    for (int i = 0; i < 32; i += 8)
        dst[(bx + ty + i) * NU + by + tx] = tile[tx][ty + i];
}

__global__ void __launch_bounds__(128) kqk(const float* __restrict__ qw) {
    int t = blockIdx.y, e = blockIdx.x, u = threadIdx.x;
    const float* q = qw + ((size_t)t * NU + e) * NU;
    const float* kt = g_KT + (size_t)t * NU * NU;
    float acc = 0.f;
#pragma unroll 8
    for (int v = 0; v < NU; ++v)
        acc = fmaf(q[v], kt[v * NU + u], acc);
    g_QK[((size_t)t * NU + e) * NU + u] = acc;
}

__global__ void __launch_bounds__(128) kvf(const float* __restrict__ vw,
                                           const float* __restrict__ fw) {
    int t = blockIdx.y, w = blockIdx.x, j = threadIdx.x;
    const float* vr = vw + ((size_t)t * NU + w) * NU;
    const float* f = fw + (size_t)t * NU * NU;
    float acc = 0.f;
#pragma unroll 8
    for (int u = 0; u < NU; ++u)
        acc = fmaf(vr[u], f[u * NU + j], acc);
    g_VF[((size_t)t * NU + w) * NU + j] = acc;
}

// ============ tiled gathered GEMM (R2 proven): dst[t][n][:] = X[eidx[t][n]] @ W[t] ============
// W source: useExt ? Wext+t : g_QK+t. 256 thr, M=64, 96KB smem.
__global__ void __launch_bounds__(256) kgemmG(const float* __restrict__ state,
                                              const int* __restrict__ eidx,
                                              const float* __restrict__ Wext,
                                              int useExt, int t,
                                              float* __restrict__ dst) {
    extern __shared__ float smem[];
    float* sX = smem;                        // [64][128]
    float4* sW4 = (float4*)(smem + 64 * NU); // [128][32]
    int n0 = blockIdx.x * 64;

    const float4* w4 = useExt ? (const float4*)(Wext + (size_t)t * NU * NU)
                              : (const float4*)(g_QK + (size_t)t * NU * NU);
#pragma unroll
    for (int i = threadIdx.x; i < 4096; i += 256) sW4[i] = w4[i];

    float4* sX4 = (float4*)sX;
#pragma unroll
    for (int i = threadIdx.x; i < 2048; i += 256) {
        int r = i >> 5, c = i & 31;
        int idx = eidx[t * PT + n0 + r];
        sX4[i] = __ldg((const float4*)(state + (size_t)idx * NU) + c);
    }
    __syncthreads();

    int tx = threadIdx.x & 31;
    int ty = threadIdx.x >> 5;
    float4 acc[8];
#pragma unroll
    for (int i = 0; i < 8; ++i) acc[i] = make_float4(0.f, 0.f, 0.f, 0.f);

#pragma unroll 4
    for (int v = 0; v < NU; ++v) {
        float4 b = sW4[v * 32 + tx];
#pragma unroll
        for (int i = 0; i < 8; ++i) {
            float a = sX[(ty * 8 + i) * NU + v];
            acc[i].x = fmaf(a, b.x, acc[i].x);
            acc[i].y = fmaf(a, b.y, acc[i].y);
            acc[i].z = fmaf(a, b.z, acc[i].z);
            acc[i].w = fmaf(a, b.w, acc[i].w);
        }
    }
#pragma unroll
    for (int i = 0; i < 8; ++i)
        ((float4*)(dst + ((size_t)t * PT + n0 + ty * 8 + i) * NU))[tx] = acc[i];
}

// ============ k1b(t): raw = hist . qkx (pure stream) ============
__global__ void __launch_bounds__(128) k1b(const float* __restrict__ hist,
                                           const int* __restrict__ eidx, int t) {
    int lane = threadIdx.x & 31;
    int warp = threadIdx.x >> 5;
    int n = blockIdx.x * 4 + warp;
    int idx = eidx[t * PT + n];

    float4 qkl = ((const float4*)(g_QKX + ((size_t)t * PT + n) * NU))[lane];
    const float4* h4 = (const float4*)(hist + (size_t)idx * NH * NU);
    float myraw = 0.f;
#pragma unroll 8
    for (int h = 0; h < NH; ++h) {
        float4 r4 = __ldcs(h4 + h * 32 + lane);
        float p = fmaf(r4.x, qkl.x, fmaf(r4.y, qkl.y, fmaf(r4.z, qkl.z, r4.w * qkl.w)));
#pragma unroll
        for (int o = 16; o; o >>= 1) p += __shfl_xor_sync(0xffffffffu, p, o);
        if (lane == h) myraw = p;
    }
    g_RAW[((size_t)t * PT + n) * NH + lane] = myraw;
}

// ---------------- k2: online softmax stats per (t,h) ----------------
__global__ void __launch_bounds__(256) k2() {
    int th = blockIdx.x;
    const float* base = g_RAW + ((size_t)(th >> 5)) * PT * NH + (th & 31);
    __shared__ float rm[256], rs[256];
    int tid = threadIdx.x;

    float m = -3.402823466e+38f, s = 0.f;
    for (int n = tid; n < PT; n += 256) {
        float x = base[(size_t)n * NH];
        if (x > m) { s = s * expf(m - x) + 1.f; m = x; }
        else s += expf(x - m);
    }
    rm[tid] = m; rs[tid] = s;
    __syncthreads();
#pragma unroll
    for (int st = 128; st; st >>= 1) {
        if (tid < st) {
            float m2 = rm[tid + st], s2 = rs[tid + st];
            float M = fmaxf(rm[tid], m2);
            rs[tid] = rs[tid] * expf(rm[tid] - M) + s2 * expf(m2 - M);
            rm[tid] = M;
        }
        __syncthreads();
    }
    if (tid == 0) { g_M[th] = rm[0]; g_S[th] = rs[0]; }
}

// ============ k3a(t): hbar = attn^T hist (pure stream) ============
__global__ void __launch_bounds__(128) k3a(const float* __restrict__ hist,
                                           const int* __restrict__ eidx, int t) {
    __shared__ float sw[4][NH];
    int lane = threadIdx.x & 31;
    int warp = threadIdx.x >> 5;
    int n = blockIdx.x * 4 + warp;
    int idx = eidx[t * PT + n];

    {
        float r = g_RAW[((size_t)t * PT + n) * NH + lane];
        sw[warp][lane] = expf(r - g_M[t * NH + lane]) / g_S[t * NH + lane];
    }
    __syncwarp();

    const float4* h4 = (const float4*)(hist + (size_t)idx * NH * NU);
    float4 hb = make_float4(0.f, 0.f, 0.f, 0.f);
#pragma unroll 8
    for (int h = 0; h < NH; ++h) {
        float4 r4 = __ldcs(h4 + h * 32 + lane);
        float wh = sw[warp][h];
        hb.x = fmaf(wh, r4.x, hb.x); hb.y = fmaf(wh, r4.y, hb.y);
        hb.z = fmaf(wh, r4.z, hb.z); hb.w = fmaf(wh, r4.w, hb.w);
    }
    ((float4*)(g_HB + ((size_t)t * PT + n) * NU))[lane] = hb;
}

// ============ kout(t): out = relu(HB @ VF) + g_Q  (single GEMM + epilogue) ============
__global__ void __launch_bounds__(256) koutG(float* __restrict__ out, int t) {
    extern __shared__ float smem[];
    float* sX = smem;
    float4* sW4 = (float4*)(smem + 64 * NU);
    int n0 = blockIdx.x * 64;
    int tx = threadIdx.x & 31;
    int ty = threadIdx.x >> 5;

    {
        const float4* w4 = (const float4*)(g_VF + (size_t)t * NU * NU);
#pragma unroll
        for (int i = threadIdx.x; i < 4096; i += 256) sW4[i] = w4[i];
        const float4* x4 = (const float4*)(g_HB + ((size_t)t * PT + n0) * NU);
        float4* sX4 = (float4*)sX;
#pragma unroll
        for (int i = threadIdx.x; i < 2048; i += 256) sX4[i] = x4[i];
    }
    __syncthreads();

    float4 acc[8];
#pragma unroll
    for (int i = 0; i < 8; ++i) acc[i] = make_float4(0.f, 0.f, 0.f, 0.f);
#pragma unroll 4
    for (int v = 0; v < NU; ++v) {
        float4 b = sW4[v * 32 + tx];
#pragma unroll
        for (int i = 0; i < 8; ++i) {
            float a = sX[(ty * 8 + i) * NU + v];
            acc[i].x = fmaf(a, b.x, acc[i].x);
            acc[i].y = fmaf(a, b.y, acc[i].y);
            acc[i].z = fmaf(a, b.z, acc[i].z);
            acc[i].w = fmaf(a, b.w, acc[i].w);
        }
    }
#pragma unroll
    for (int i = 0; i < 8; ++i) {
        size_t row = (size_t)t * PT + n0 + ty * 8 + i;
        float4 q4 = ((const float4*)(g_Q + row * NU))[tx];
        float4 r;
        r.x = fmaxf(acc[i].x, 0.f) + q4.x;
        r.y = fmaxf(acc[i].y, 0.f) + q4.y;
        r.z = fmaxf(acc[i].z, 0.f) + q4.z;
        r.w = fmaxf(acc[i].w, 0.f) + q4.w;
        ((float4*)(out + row * NU))[tx] = r;
    }
}

// ---------------- launch: multi-stream fork-join pipeline ----------------
extern "C" void kernel_launch(void* const* d_in, const int* in_sizes, int n_in,
                              void* d_out, int out_size) {
    const float* state = (const float*)d_in[0];
    const float* hist  = (const float*)d_in[1];
    const int*   eidx  = (const int*)d_in[2];
    const float* qw    = (const float*)d_in[3];
    const float* kw    = (const float*)d_in[4];
    const float* vw    = (const float*)d_in[5];
    const float* fw    = (const float*)d_in[6];
    float* out = (float*)d_out;

    const int GSMEM = (64 * NU + 4096 * 4) * 4;  // 96 KB

    static bool init_done = false;
    static cudaStream_t s1, s2;
    static cudaEvent_t eP, gE[NT], hE[NT], e1, fE;
    static float *p_QKX, *p_Q;
    if (!init_done) {
        cudaFuncSetAttribute(kgemmG, cudaFuncAttributeMaxDynamicSharedMemorySize, GSMEM);
        cudaFuncSetAttribute(koutG, cudaFuncAttributeMaxDynamicSharedMemorySize, GSMEM);
        cudaStreamCreateWithFlags(&s1, cudaStreamNonBlocking);
        cudaStreamCreateWithFlags(&s2, cudaStreamNonBlocking);
        cudaEventCreateWithFlags(&eP, cudaEventDisableTiming);
        for (int t = 0; t < NT; ++t) {
            cudaEventCreateWithFlags(&gE[t], cudaEventDisableTiming);
            cudaEventCreateWithFlags(&hE[t], cudaEventDisableTiming);
        }
        cudaEventCreateWithFlags(&e1, cudaEventDisableTiming);
        cudaEventCreateWithFlags(&fE, cudaEventDisableTiming);
        cudaGetSymbolAddress((void**)&p_QKX, g_QKX);
        cudaGetSymbolAddress((void**)&p_Q, g_Q);
        init_done = true;
    }

    // ---- s0 (capture stream): prep + per-type QKX GEMMs ----
    ktrans<<<dim3(4, 4, NT), dim3(32, 8)>>>(kw);
    kqk<<<dim3(NU, NT), NU>>>(qw);
    cudaEventRecord(eP, 0);
    for (int t = 0; t < NT; ++t) {
        kgemmG<<<PT / 64, 256, GSMEM>>>(state, eidx, nullptr, 0, t, p_QKX);
        cudaEventRecord(gE[t], 0);
    }

    // ---- s1: hist stream pass 1, softmax stats, hist stream pass 2 ----
    for (int t = 0; t < NT; ++t) {
        cudaStreamWaitEvent(s1, gE[t], 0);
        k1b<<<PT / 4, 128, 0, s1>>>(hist, eidx, t);
    }
    k2<<<NT * NH, 256, 0, s1>>>();
    for (int t = 0; t < NT; ++t) {
        k3a<<<PT / 4, 128, 0, s1>>>(hist, eidx, t);
        cudaEventRecord(hE[t], s1);
    }
    cudaEventRecord(e1, s1);

    // ---- s2: independent GEMVs (hidden under s1), then per-type epilogue GEMMs ----
    cudaStreamWaitEvent(s2, eP, 0);
    kvf<<<dim3(NU, NT), NU, 0, s2>>>(vw, fw);
    for (int t = 0; t < NT; ++t)
        kgemmG<<<PT / 64, 256, GSMEM, s2>>>(state, eidx, qw, 1, t, p_Q);
    for (int t = 0; t < NT; ++t) {
        cudaStreamWaitEvent(s2, hE[t], 0);
        koutG<<<PT / 64, 256, GSMEM, s2>>>(out, t);
    }
    cudaEventRecord(fE, s2);

    // ---- join everything back to the capture stream ----
    cudaStreamWaitEvent(0, e1, 0);
    cudaStreamWaitEvent(0, fE, 0);
}

// round 7
// speedup vs baseline: 1.1643x; 1.0311x over previous
#include <cuda_runtime.h>
#include <math.h>

#define NT 4
#define PT 8192
#define NH 32
#define NU 128

// ---------------- scratch (device globals; no allocations) ----------------
__device__ float g_KT[NT * NU * NU];
__device__ float g_QK[NT * NU * NU];           // q_w @ k_w^T
__device__ float g_VF[NT * NU * NU];           // v_w @ fc_w
__device__ float g_Q[(size_t)NT * PT * NU];    // q = x @ q_w
__device__ float g_QKX[(size_t)NT * PT * NU];  // x @ QK
__device__ float g_HB[(size_t)NT * PT * NU];   // attn-weighted hist
__device__ float g_RAW[(size_t)NT * PT * NH];
__device__ float g_M[NT * NH];
__device__ float g_S[NT * NH];

// ---------------- prep ----------------
__global__ void __launch_bounds__(256) ktrans(const float* __restrict__ kw) {
    __shared__ float tile[32][33];
    int t = blockIdx.z;
    int bx = blockIdx.x * 32, by = blockIdx.y * 32;
    const float* src = kw + (size_t)t * NU * NU;
    float* dst = g_KT + (size_t)t * NU * NU;
    int tx = threadIdx.x, ty = threadIdx.y;
#pragma unroll
    for (int i = 0; i < 32; i += 8)
        tile[ty + i][tx] = src[(by + ty + i) * NU + bx + tx];
    __syncthreads();
#pragma unroll
    for (int i = 0; i < 32; i += 8)
        dst[(bx + ty + i) * NU + by + tx] = tile[tx][ty + i];
}

__global__ void __launch_bounds__(128) kqk(const float* __restrict__ qw) {
    int t = blockIdx.y, e = blockIdx.x, u = threadIdx.x;
    const float* q = qw + ((size_t)t * NU + e) * NU;
    const float* kt = g_KT + (size_t)t * NU * NU;
    float acc = 0.f;
#pragma unroll 8
    for (int v = 0; v < NU; ++v)
        acc = fmaf(q[v], kt[v * NU + u], acc);
    g_QK[((size_t)t * NU + e) * NU + u] = acc;
}

__global__ void __launch_bounds__(128) kvf(const float* __restrict__ vw,
                                           const float* __restrict__ fw) {
    int t = blockIdx.y, w = blockIdx.x, j = threadIdx.x;
    const float* vr = vw + ((size_t)t * NU + w) * NU;
    const float* f = fw + (size_t)t * NU * NU;
    float acc = 0.f;
#pragma unroll 8
    for (int u = 0; u < NU; ++u)
        acc = fmaf(vr[u], f[u * NU + j], acc);
    g_VF[((size_t)t * NU + w) * NU + j] = acc;
}

// ============ split-N gathered GEMM: dst[t][n][64*half..] = X[eidx] @ W[:, half] ============
// 256 thr, M=64, N-half=64. smem = X 32KB + W-half 32KB = 64KB -> 3 CTAs/SM.
__global__ void __launch_bounds__(256) kgemmH(const float* __restrict__ state,
                                              const int* __restrict__ eidx,
                                              const float* __restrict__ Wext,
                                              int useExt, int t,
                                              float* __restrict__ dst) {
    extern __shared__ float smem[];
    float* sX = smem;                        // [64][128] = 32KB
    float4* sW4 = (float4*)(smem + 64 * NU); // [128][16] float4 = 32KB
    int n0 = blockIdx.x * 64;
    int half = blockIdx.y;

    const float4* w4 = (useExt ? (const float4*)(Wext + (size_t)t * NU * NU)
                               : (const float4*)(g_QK + (size_t)t * NU * NU));
#pragma unroll
    for (int i = threadIdx.x; i < 2048; i += 256)
        sW4[i] = w4[(i >> 4) * 32 + half * 16 + (i & 15)];

    float4* sX4 = (float4*)sX;
#pragma unroll
    for (int i = threadIdx.x; i < 2048; i += 256) {
        int r = i >> 5, c = i & 31;
        int idx = eidx[t * PT + n0 + r];
        sX4[i] = __ldg((const float4*)(state + (size_t)idx * NU) + c);
    }
    __syncthreads();

    int tx = threadIdx.x & 15;   // float4 col within half
    int ty = threadIdx.x >> 4;   // 16 groups of 4 rows
    float4 acc[4];
#pragma unroll
    for (int i = 0; i < 4; ++i) acc[i] = make_float4(0.f, 0.f, 0.f, 0.f);

#pragma unroll 4
    for (int v = 0; v < NU; ++v) {
        float4 b = sW4[v * 16 + tx];
#pragma unroll
        for (int i = 0; i < 4; ++i) {
            float a = sX[(ty * 4 + i) * NU + v];
            acc[i].x = fmaf(a, b.x, acc[i].x);
            acc[i].y = fmaf(a, b.y, acc[i].y);
            acc[i].z = fmaf(a, b.z, acc[i].z);
            acc[i].w = fmaf(a, b.w, acc[i].w);
        }
    }
#pragma unroll
    for (int i = 0; i < 4; ++i)
        ((float4*)(dst + ((size_t)t * PT + n0 + ty * 4 + i) * NU))[half * 16 + tx] = acc[i];
}

// ============ k1b(t): raw = hist . qkx — quarter-warp rows, 3-shfl reduce ============
__global__ void __launch_bounds__(128) k1b(const float* __restrict__ hist,
                                           const int* __restrict__ eidx, int t) {
    int lane = threadIdx.x & 31;
    int warp = threadIdx.x >> 5;
    int n = blockIdx.x * 4 + warp;
    int idx = eidx[t * PT + n];
    int g = lane >> 3;   // row within 4-row group
    int c = lane & 7;    // 16B chunk within 128B sub-row

    const float4* qkrow = (const float4*)(g_QKX + ((size_t)t * PT + n) * NU);
    float4 qk[4];
#pragma unroll
    for (int j = 0; j < 4; ++j) qk[j] = __ldg(qkrow + j * 8 + c);

    const float* hb = hist + (size_t)idx * NH * NU;
    float* rawdst = g_RAW + ((size_t)t * PT + n) * NH;
#pragma unroll
    for (int i = 0; i < 8; ++i) {
        const float4* rowp = (const float4*)(hb + (4 * i + g) * NU);
        float4 v0 = __ldcs(rowp + 0 * 8 + c);
        float4 v1 = __ldcs(rowp + 1 * 8 + c);
        float4 v2 = __ldcs(rowp + 2 * 8 + c);
        float4 v3 = __ldcs(rowp + 3 * 8 + c);
        float p = 0.f;
        p = fmaf(v0.x, qk[0].x, p); p = fmaf(v0.y, qk[0].y, p);
        p = fmaf(v0.z, qk[0].z, p); p = fmaf(v0.w, qk[0].w, p);
        p = fmaf(v1.x, qk[1].x, p); p = fmaf(v1.y, qk[1].y, p);
        p = fmaf(v1.z, qk[1].z, p); p = fmaf(v1.w, qk[1].w, p);
        p = fmaf(v2.x, qk[2].x, p); p = fmaf(v2.y, qk[2].y, p);
        p = fmaf(v2.z, qk[2].z, p); p = fmaf(v2.w, qk[2].w, p);
        p = fmaf(v3.x, qk[3].x, p); p = fmaf(v3.y, qk[3].y, p);
        p = fmaf(v3.z, qk[3].z, p); p = fmaf(v3.w, qk[3].w, p);
        p += __shfl_xor_sync(0xffffffffu, p, 4);
        p += __shfl_xor_sync(0xffffffffu, p, 2);
        p += __shfl_xor_sync(0xffffffffu, p, 1);
        if (c == 0) rawdst[4 * i + g] = p;
    }
}

// ---------------- k2: online softmax stats per (t,h) ----------------
__global__ void __launch_bounds__(256) k2() {
    int th = blockIdx.x;
    const float* base = g_RAW + ((size_t)(th >> 5)) * PT * NH + (th & 31);
    __shared__ float rm[256], rs[256];
    int tid = threadIdx.x;

    float m = -3.402823466e+38f, s = 0.f;
    for (int n = tid; n < PT; n += 256) {
        float x = base[(size_t)n * NH];
        if (x > m) { s = s * expf(m - x) + 1.f; m = x; }
        else s += expf(x - m);
    }
    rm[tid] = m; rs[tid] = s;
    __syncthreads();
#pragma unroll
    for (int st = 128; st; st >>= 1) {
        if (tid < st) {
            float m2 = rm[tid + st], s2 = rs[tid + st];
            float M = fmaxf(rm[tid], m2);
            rs[tid] = rs[tid] * expf(rm[tid] - M) + s2 * expf(m2 - M);
            rm[tid] = M;
        }
        __syncthreads();
    }
    if (tid == 0) { g_M[th] = rm[0]; g_S[th] = rs[0]; }
}

// ============ k3a(t): hbar = attn^T hist (pure stream, lane-owns-column) ============
__global__ void __launch_bounds__(128) k3a(const float* __restrict__ hist,
                                           const int* __restrict__ eidx, int t) {
    __shared__ float sw[4][NH];
    int lane = threadIdx.x & 31;
    int warp = threadIdx.x >> 5;
    int n = blockIdx.x * 4 + warp;
    int idx = eidx[t * PT + n];

    {
        float r = g_RAW[((size_t)t * PT + n) * NH + lane];
        sw[warp][lane] = expf(r - g_M[t * NH + lane]) / g_S[t * NH + lane];
    }
    __syncwarp();

    const float4* h4 = (const float4*)(hist + (size_t)idx * NH * NU);
    float4 hb = make_float4(0.f, 0.f, 0.f, 0.f);
#pragma unroll 8
    for (int h = 0; h < NH; ++h) {
        float4 r4 = __ldcs(h4 + h * 32 + lane);
        float wh = sw[warp][h];
        hb.x = fmaf(wh, r4.x, hb.x); hb.y = fmaf(wh, r4.y, hb.y);
        hb.z = fmaf(wh, r4.z, hb.z); hb.w = fmaf(wh, r4.w, hb.w);
    }
    ((float4*)(g_HB + ((size_t)t * PT + n) * NU))[lane] = hb;
}

// ============ kout(t): out = relu(HB @ VF) + g_Q  (split-N GEMM + epilogue) ============
__global__ void __launch_bounds__(256) koutH(float* __restrict__ out, int t) {
    extern __shared__ float smem[];
    float* sX = smem;
    float4* sW4 = (float4*)(smem + 64 * NU);
    int n0 = blockIdx.x * 64;
    int half = blockIdx.y;

    {
        const float4* w4 = (const float4*)(g_VF + (size_t)t * NU * NU);
#pragma unroll
        for (int i = threadIdx.x; i < 2048; i += 256)
            sW4[i] = w4[(i >> 4) * 32 + half * 16 + (i & 15)];
        const float4* x4 = (const float4*)(g_HB + ((size_t)t * PT + n0) * NU);
        float4* sX4 = (float4*)sX;
#pragma unroll
        for (int i = threadIdx.x; i < 2048; i += 256) sX4[i] = x4[i];
    }
    __syncthreads();

    int tx = threadIdx.x & 15;
    int ty = threadIdx.x >> 4;
    float4 acc[4];
#pragma unroll
    for (int i = 0; i < 4; ++i) acc[i] = make_float4(0.f, 0.f, 0.f, 0.f);
#pragma unroll 4
    for (int v = 0; v < NU; ++v) {
        float4 b = sW4[v * 16 + tx];
#pragma unroll
        for (int i = 0; i < 4; ++i) {
            float a = sX[(ty * 4 + i) * NU + v];
            acc[i].x = fmaf(a, b.x, acc[i].x);
            acc[i].y = fmaf(a, b.y, acc[i].y);
            acc[i].z = fmaf(a, b.z, acc[i].z);
            acc[i].w = fmaf(a, b.w, acc[i].w);
        }
    }
#pragma unroll
    for (int i = 0; i < 4; ++i) {
        size_t row = (size_t)t * PT + n0 + ty * 4 + i;
        float4 q4 = ((const float4*)(g_Q + row * NU))[half * 16 + tx];
        float4 r;
        r.x = fmaxf(acc[i].x, 0.f) + q4.x;
        r.y = fmaxf(acc[i].y, 0.f) + q4.y;
        r.z = fmaxf(acc[i].z, 0.f) + q4.z;
        r.w = fmaxf(acc[i].w, 0.f) + q4.w;
        ((float4*)(out + row * NU))[half * 16 + tx] = r;
    }
}

// ---------------- launch: multi-stream fork-join pipeline ----------------
extern "C" void kernel_launch(void* const* d_in, const int* in_sizes, int n_in,
                              void* d_out, int out_size) {
    const float* state = (const float*)d_in[0];
    const float* hist  = (const float*)d_in[1];
    const int*   eidx  = (const int*)d_in[2];
    const float* qw    = (const float*)d_in[3];
    const float* kw    = (const float*)d_in[4];
    const float* vw    = (const float*)d_in[5];
    const float* fw    = (const float*)d_in[6];
    float* out = (float*)d_out;

    const int GSMEM = 64 * 1024;   // X 32KB + W-half 32KB

    static bool init_done = false;
    static cudaStream_t s1, s2;
    static cudaEvent_t eP, gE[NT], hE[NT], e1, fE;
    static float *p_QKX, *p_Q;
    if (!init_done) {
        cudaFuncSetAttribute(kgemmH, cudaFuncAttributeMaxDynamicSharedMemorySize, GSMEM);
        cudaFuncSetAttribute(koutH, cudaFuncAttributeMaxDynamicSharedMemorySize, GSMEM);
        int lo, hi;
        cudaDeviceGetStreamPriorityRange(&lo, &hi);
        cudaStreamCreateWithPriority(&s1, cudaStreamNonBlocking, hi); // streams: high
        cudaStreamCreateWithPriority(&s2, cudaStreamNonBlocking, lo); // gemvs: low
        cudaEventCreateWithFlags(&eP, cudaEventDisableTiming);
        for (int t = 0; t < NT; ++t) {
            cudaEventCreateWithFlags(&gE[t], cudaEventDisableTiming);
            cudaEventCreateWithFlags(&hE[t], cudaEventDisableTiming);
        }
        cudaEventCreateWithFlags(&e1, cudaEventDisableTiming);
        cudaEventCreateWithFlags(&fE, cudaEventDisableTiming);
        cudaGetSymbolAddress((void**)&p_QKX, g_QKX);
        cudaGetSymbolAddress((void**)&p_Q, g_Q);
        init_done = true;
    }

    // ---- s0 (capture stream): prep + per-type QKX GEMMs ----
    ktrans<<<dim3(4, 4, NT), dim3(32, 8)>>>(kw);
    kqk<<<dim3(NU, NT), NU>>>(qw);
    cudaEventRecord(eP, 0);
    for (int t = 0; t < NT; ++t) {
        kgemmH<<<dim3(PT / 64, 2), 256, GSMEM>>>(state, eidx, nullptr, 0, t, p_QKX);
        cudaEventRecord(gE[t], 0);
    }

    // ---- s1 (high prio): hist pass 1, stats, hist pass 2 ----
    for (int t = 0; t < NT; ++t) {
        cudaStreamWaitEvent(s1, gE[t], 0);
        k1b<<<PT / 4, 128, 0, s1>>>(hist, eidx, t);
    }
    k2<<<NT * NH, 256, 0, s1>>>();
    for (int t = 0; t < NT; ++t) {
        k3a<<<PT / 4, 128, 0, s1>>>(hist, eidx, t);
        cudaEventRecord(hE[t], s1);
    }
    cudaEventRecord(e1, s1);

    // ---- s2 (low prio): independent GEMVs under the streams, then epilogues ----
    cudaStreamWaitEvent(s2, eP, 0);
    kvf<<<dim3(NU, NT), NU, 0, s2>>>(vw, fw);
    for (int t = 0; t < NT; ++t)
        kgemmH<<<dim3(PT / 64, 2), 256, GSMEM, s2>>>(state, eidx, qw, 1, t, p_Q);
    for (int t = 0; t < NT; ++t) {
        cudaStreamWaitEvent(s2, hE[t], 0);
        koutH<<<dim3(PT / 64, 2), 256, GSMEM, s2>>>(out, t);
    }
    cudaEventRecord(fE, s2);

    // ---- join ----
    cudaStreamWaitEvent(0, e1, 0);
    cudaStreamWaitEvent(0, fE, 0);
}